// round 3
// baseline (speedup 1.0000x reference)
#include <cuda_runtime.h>

#define SEQ   4096
#define BATCH 8
#define DM    1024
#define MTOT  (SEQ*BATCH)   // 32768

// ---------------- scratch (device globals; no allocations allowed) ----------
__device__ float g_Q[(size_t)MTOT * DM];
__device__ float g_K[(size_t)MTOT * DM];
__device__ float g_V[(size_t)MTOT * DM];
__device__ float g_AO[(size_t)MTOT * DM];

// ---------------- fp32 NT SGEMM: C[M,N] = A[M,K] * B[N,K]^T + bias ----------
// 128x128 tile, BK=16, 256 threads, 8x8 per thread. M,N,K multiples of tile.
// MODE 0: C[row*N + col]
// MODE 1: permuted store for the final (A,B,D) transpose:
//         row = b*4096 + a'  ->  out[a'*8192 + b*1024 + col]
template <int MODE>
__device__ __forceinline__ void sgemm_body(const float* __restrict__ A,
                                           const float* __restrict__ B,
                                           const float* __restrict__ bias,
                                           float* __restrict__ C,
                                           int N, int K)
{
    __shared__ __align__(16) float As[16][132];
    __shared__ __align__(16) float Bs[16][132];

    const int tid = threadIdx.x;
    const int tx  = tid & 15;          // 0..15  -> col group
    const int ty  = tid >> 4;          // 0..15  -> row group
    const int row0 = blockIdx.y * 128;
    const int col0 = blockIdx.x * 128;

    float acc[8][8];
#pragma unroll
    for (int i = 0; i < 8; i++)
#pragma unroll
        for (int j = 0; j < 8; j++) acc[i][j] = 0.0f;

    const float* Aptr = A + (size_t)row0 * K;
    const float* Bptr = B + (size_t)col0 * K;

    for (int k0 = 0; k0 < K; k0 += 16) {
        // 128 rows x 16 k per operand = 512 float4; 2 per thread per operand
#pragma unroll
        for (int u = 0; u < 2; u++) {
            int f  = tid + u * 256;        // 0..511
            int r  = f >> 2;               // row within tile
            int kk = (f & 3) * 4;          // k within tile
            float4 va = *(const float4*)(Aptr + (size_t)r * K + k0 + kk);
            As[kk + 0][r] = va.x; As[kk + 1][r] = va.y;
            As[kk + 2][r] = va.z; As[kk + 3][r] = va.w;
            float4 vb = *(const float4*)(Bptr + (size_t)r * K + k0 + kk);
            Bs[kk + 0][r] = vb.x; Bs[kk + 1][r] = vb.y;
            Bs[kk + 2][r] = vb.z; Bs[kk + 3][r] = vb.w;
        }
        __syncthreads();

#pragma unroll
        for (int k = 0; k < 16; k++) {
            float a[8], b[8];
            float4 a0 = *(const float4*)(&As[k][ty * 8]);
            float4 a1 = *(const float4*)(&As[k][ty * 8 + 4]);
            float4 b0 = *(const float4*)(&Bs[k][tx * 8]);
            float4 b1 = *(const float4*)(&Bs[k][tx * 8 + 4]);
            a[0]=a0.x; a[1]=a0.y; a[2]=a0.z; a[3]=a0.w;
            a[4]=a1.x; a[5]=a1.y; a[6]=a1.z; a[7]=a1.w;
            b[0]=b0.x; b[1]=b0.y; b[2]=b0.z; b[3]=b0.w;
            b[4]=b1.x; b[5]=b1.y; b[6]=b1.z; b[7]=b1.w;
#pragma unroll
            for (int i = 0; i < 8; i++)
#pragma unroll
                for (int j = 0; j < 8; j++)
                    acc[i][j] += a[i] * b[j];
        }
        __syncthreads();
    }

#pragma unroll
    for (int i = 0; i < 8; i++) {
        int r = row0 + ty * 8 + i;
#pragma unroll
        for (int j = 0; j < 8; j++) {
            int c = col0 + tx * 8 + j;
            float v = acc[i][j] + bias[c];
            if (MODE == 0) {
                C[(size_t)r * N + c] = v;
            } else {
                int arow = r & 4095;       // a'
                int ob   = r >> 12;        // b
                C[(size_t)arow * (BATCH * DM) + (size_t)ob * DM + c] = v;
            }
        }
    }
}

__global__ void qkv_gemm(const float* __restrict__ q, const float* __restrict__ k,
                         const float* __restrict__ v,
                         const float* __restrict__ Wq, const float* __restrict__ bq,
                         const float* __restrict__ Wk, const float* __restrict__ bk,
                         const float* __restrict__ Wv, const float* __restrict__ bv)
{
    const float* A; const float* B; const float* bias; float* C;
    if (blockIdx.z == 0)      { A = q; B = Wq; bias = bq; C = g_Q; }
    else if (blockIdx.z == 1) { A = k; B = Wk; bias = bk; C = g_K; }
    else                      { A = v; B = Wv; bias = bv; C = g_V; }
    sgemm_body<0>(A, B, bias, C, DM, DM);
}

__global__ void out_gemm(const float* __restrict__ Wo, const float* __restrict__ bo,
                         float* __restrict__ out)
{
    sgemm_body<1>(g_AO, Wo, bo, out, DM, DM);
}

// ---------------- attention: per (a,b) pair, 16x16 scores across HEADS ------
// One warp per pair, 2 warps per block. Exact sparsemax (sort-based simplex
// projection) over 16-wide rows with combined scale 1/(sqrt(64)*alpha)=1/12.
// Output written directly in the bug-faithful permuted layout:
//   g_AO[(b*4096 + h*256 + a/16)*1024 + (a%16)*64 + d]
__global__ void attn_kernel()
{
    __shared__ float qs[2][16][65];
    __shared__ float ks[2][16][65];
    __shared__ float vs[2][16][65];
    __shared__ float ss[2][16][17];

    const int w = threadIdx.x >> 5;      // warp in block (0..1)
    const int l = threadIdx.x & 31;      // lane
    const int p = blockIdx.x * 2 + w;    // pair id 0..32767  (row of Q/K/V mats)
    const int a = p >> 3;
    const int b = p & 7;

    const float* Qg = g_Q + (size_t)p * DM;
    const float* Kg = g_K + (size_t)p * DM;
    const float* Vg = g_V + (size_t)p * DM;

    // load 16x64 tiles (1024 floats each) cooperatively
#pragma unroll
    for (int i = 0; i < 8; i++) {
        int idx4 = (l + 32 * i) * 4;
        int r = idx4 >> 6, c = idx4 & 63;
        float4 vq = *(const float4*)(Qg + idx4);
        qs[w][r][c] = vq.x; qs[w][r][c+1] = vq.y; qs[w][r][c+2] = vq.z; qs[w][r][c+3] = vq.w;
        float4 vk = *(const float4*)(Kg + idx4);
        ks[w][r][c] = vk.x; ks[w][r][c+1] = vk.y; ks[w][r][c+2] = vk.z; ks[w][r][c+3] = vk.w;
        float4 vv = *(const float4*)(Vg + idx4);
        vs[w][r][c] = vv.x; vs[w][r][c+1] = vv.y; vs[w][r][c+2] = vv.z; vs[w][r][c+3] = vv.w;
    }
    __syncwarp();

    // scores: lane l owns (h = l>>1, g in [ (l&1)*8, +8 ))
    {
        const int h  = l >> 1;
        const int g0 = (l & 1) * 8;
        float acc[8] = {0, 0, 0, 0, 0, 0, 0, 0};
#pragma unroll
        for (int d = 0; d < 64; d++) {
            float qv = qs[w][h][d];
#pragma unroll
            for (int j = 0; j < 8; j++) acc[j] += qv * ks[w][g0 + j][d];
        }
        // zs = (QK^T / sqrt(hd)) / alpha = QK^T / 12
        const float sc = 1.0f / 12.0f;
#pragma unroll
        for (int j = 0; j < 8; j++) ss[w][h][g0 + j] = acc[j] * sc;
    }
    __syncwarp();

    // sparsemax per row: lanes 0..15, one row each
    if (l < 16) {
        float z[16];
#pragma unroll
        for (int g = 0; g < 16; g++) z[g] = ss[w][l][g];
        // selection sort, descending (fully unrolled -> registers)
#pragma unroll
        for (int i = 0; i < 15; i++)
#pragma unroll
            for (int j = i + 1; j < 16; j++)
                if (z[j] > z[i]) { float t = z[i]; z[i] = z[j]; z[j] = t; }
        float cum = 0.0f, tausum = 0.0f;
        int kk = 0;
#pragma unroll
        for (int i = 0; i < 16; i++) {
            cum += z[i];
            if (z[i] * (float)(i + 1) > cum - 1.0f) { kk = i + 1; tausum = cum; }
        }
        float tau = (tausum - 1.0f) / (float)kk;
#pragma unroll
        for (int g = 0; g < 16; g++)
            ss[w][l][g] = fmaxf(ss[w][l][g] - tau, 0.0f);
    }
    __syncwarp();

    // attn_out: lane l owns (h = l>>1, d in [(l&1)*32, +32))
    {
        const int h  = l >> 1;
        const int d0 = (l & 1) * 32;
        float o[32];
#pragma unroll
        for (int d = 0; d < 32; d++) o[d] = 0.0f;
#pragma unroll
        for (int g = 0; g < 16; g++) {
            float av = ss[w][h][g];
#pragma unroll
            for (int d = 0; d < 32; d++) o[d] += av * vs[w][g][d0 + d];
        }
        // bug-faithful reshape: row' = b*4096 + h*256 + a/16, col = (a%16)*64 + d
        const int rowp = b * 4096 + h * 256 + (a >> 4);
        const int colb = (a & 15) * 64 + d0;
        float* dst = g_AO + (size_t)rowp * DM + colb;
#pragma unroll
        for (int d4 = 0; d4 < 32; d4 += 4) {
            float4 v4 = make_float4(o[d4], o[d4 + 1], o[d4 + 2], o[d4 + 3]);
            *(float4*)(dst + d4) = v4;
        }
    }
}

// ---------------- launch -----------------------------------------------------
extern "C" void kernel_launch(void* const* d_in, const int* in_sizes, int n_in,
                              void* d_out, int out_size)
{
    const float* query = (const float*)d_in[0];
    const float* key   = (const float*)d_in[1];
    const float* value = (const float*)d_in[2];
    const float* Wq = (const float*)d_in[3];
    const float* bq = (const float*)d_in[4];
    const float* Wk = (const float*)d_in[5];
    const float* bk = (const float*)d_in[6];
    const float* Wv = (const float*)d_in[7];
    const float* bv = (const float*)d_in[8];
    const float* Wo = (const float*)d_in[9];
    const float* bo = (const float*)d_in[10];
    float* out = (float*)d_out;

    // Q/K/V projections: 3 x (32768x1024x1024) NT GEMM
    dim3 g1(DM / 128, MTOT / 128, 3);
    qkv_gemm<<<g1, 256>>>(query, key, value, Wq, bq, Wk, bk, Wv, bv);

    // attention + sparsemax + permuted scratch write
    attn_kernel<<<MTOT / 2, 64>>>();

    // output projection with final (A,B,D) transpose in epilogue
    dim3 g2(DM / 128, MTOT / 128, 1);
    out_gemm<<<g2, 256>>>(Wo, bo, out);
}

// round 5
// speedup vs baseline: 1.3798x; 1.3798x over previous
#include <cuda_runtime.h>
#include <cstdint>

#define SEQ   4096
#define BATCH 8
#define DM    1024
#define MTOT  (SEQ*BATCH)   // 32768

// ---------------- scratch (device globals; no allocations allowed) ----------
__device__ float g_Q[(size_t)MTOT * DM];
__device__ float g_K[(size_t)MTOT * DM];
__device__ float g_V[(size_t)MTOT * DM];
__device__ float g_AO[(size_t)MTOT * DM];

// ---------------- helpers ----------------------------------------------------
static __device__ __forceinline__ uint32_t smem_u32(const void* p) {
    return (uint32_t)__cvta_generic_to_shared(p);
}

// split fp32 v into tf32 hi + tf32 lo (v ~= hi + lo, ~22 bit effective mantissa)
static __device__ __forceinline__ void split_tf32(float v, uint32_t& h, uint32_t& l) {
    uint32_t hb;
    asm("cvt.rna.tf32.f32 %0, %1;" : "=r"(hb) : "f"(v));
    float r = v - __uint_as_float(hb);
    uint32_t lb;
    asm("cvt.rna.tf32.f32 %0, %1;" : "=r"(lb) : "f"(r));
    h = hb; l = lb;
}

static __device__ __forceinline__ void mma_tf32(float* c, const uint32_t* a, const uint32_t* b) {
    asm volatile(
        "mma.sync.aligned.m16n8k8.row.col.f32.tf32.tf32.f32 "
        "{%0,%1,%2,%3}, {%4,%5,%6,%7}, {%8,%9}, {%0,%1,%2,%3};"
        : "+f"(c[0]), "+f"(c[1]), "+f"(c[2]), "+f"(c[3])
        : "r"(a[0]), "r"(a[1]), "r"(a[2]), "r"(a[3]), "r"(b[0]), "r"(b[1]));
}

// ---------------- 3xTF32 NT GEMM: C[M,N] = A[M,K] * B[N,K]^T + bias ---------
// 128x128x32 CTA tile, 256 threads = 8 warps (2m x 4n), warp tile 64x32.
// Raw fp32 tiles double-buffered via cp.async; hi/lo split at fragment load.
// Smem: per stage A[128][36] + B[128][36] floats (pad 36 -> conflict-free frags)
// MODE 0: C[row*N + col]
// MODE 1: permuted final store: row = b*4096+a' -> out[a'*8192 + b*1024 + col]
#define KPAD     36
#define TILE_F   (128 * KPAD)       // 4608 floats per operand tile
#define STAGE_F  (2 * TILE_F)       // 9216 floats per stage
#define SMEM_BYTES (2 * STAGE_F * 4)  // 73728 bytes

template <int MODE>
__device__ __forceinline__ void tgemm_body(const float* __restrict__ A,
                                           const float* __restrict__ B,
                                           const float* __restrict__ bias,
                                           float* __restrict__ C,
                                           int N, int K)
{
    extern __shared__ float sm[];
    const int tid  = threadIdx.x;
    const int lane = tid & 31;
    const int wid  = tid >> 5;
    const int wm   = wid >> 2;      // 0..1
    const int wn   = wid & 3;       // 0..3
    const int row0 = blockIdx.y * 128;
    const int col0 = blockIdx.x * 128;

    const float* Ag = A + (size_t)row0 * K;
    const float* Bg = B + (size_t)col0 * K;

    float acc[4][4][4];
#pragma unroll
    for (int i = 0; i < 4; i++)
#pragma unroll
        for (int j = 0; j < 4; j++)
#pragma unroll
            for (int r = 0; r < 4; r++) acc[i][j][r] = 0.0f;

    const int nk = K >> 5;

    // stage loader: 128 rows x 32 floats per operand = 1024 float4; 4/thread
#define LOAD_STAGE(s, k0)                                                     \
    {                                                                         \
        _Pragma("unroll")                                                     \
        for (int u = 0; u < 4; u++) {                                         \
            int f   = tid + u * 256;                                          \
            int row = f >> 3;                                                 \
            int c4  = (f & 7) * 4;                                            \
            uint32_t da = smem_u32(sm + (s) * STAGE_F + row * KPAD + c4);     \
            const float* ga = Ag + (size_t)row * K + (k0) + c4;               \
            asm volatile("cp.async.cg.shared.global [%0], [%1], 16;"          \
                         :: "r"(da), "l"(ga));                                \
            uint32_t db = smem_u32(sm + (s) * STAGE_F + TILE_F + row * KPAD + c4); \
            const float* gb = Bg + (size_t)row * K + (k0) + c4;               \
            asm volatile("cp.async.cg.shared.global [%0], [%1], 16;"          \
                         :: "r"(db), "l"(gb));                                \
        }                                                                     \
        asm volatile("cp.async.commit_group;" ::: "memory");                  \
    }

    LOAD_STAGE(0, 0);

    for (int kb = 0; kb < nk; kb++) {
        if (kb + 1 < nk) {
            LOAD_STAGE((kb + 1) & 1, (kb + 1) << 5);
            asm volatile("cp.async.wait_group 1;" ::: "memory");
        } else {
            asm volatile("cp.async.wait_group 0;" ::: "memory");
        }
        __syncthreads();

        const float* As = sm + (kb & 1) * STAGE_F;
        const float* Bs = As + TILE_F;

#pragma unroll
        for (int ks = 0; ks < 4; ks++) {
            const int kc = ks * 8 + (lane & 3);

            // B fragments for this warp's 4 n-atoms (split in registers)
            uint32_t bh[4][2], bl[4][2];
            const int rB = wn * 32 + (lane >> 2);
#pragma unroll
            for (int na = 0; na < 4; na++) {
                float v0 = Bs[(rB + na * 8) * KPAD + kc];
                float v1 = Bs[(rB + na * 8) * KPAD + kc + 4];
                split_tf32(v0, bh[na][0], bl[na][0]);
                split_tf32(v1, bh[na][1], bl[na][1]);
            }

            const int rA = wm * 64 + (lane >> 2);
#pragma unroll
            for (int ma = 0; ma < 4; ma++) {
                float u0 = As[(rA + ma * 16)     * KPAD + kc];
                float u1 = As[(rA + ma * 16 + 8) * KPAD + kc];
                float u2 = As[(rA + ma * 16)     * KPAD + kc + 4];
                float u3 = As[(rA + ma * 16 + 8) * KPAD + kc + 4];
                uint32_t ah[4], al[4];
                split_tf32(u0, ah[0], al[0]);
                split_tf32(u1, ah[1], al[1]);
                split_tf32(u2, ah[2], al[2]);
                split_tf32(u3, ah[3], al[3]);
#pragma unroll
                for (int na = 0; na < 4; na++) {
                    mma_tf32(acc[ma][na], ah, bh[na]);   // hi*hi
                    mma_tf32(acc[ma][na], al, bh[na]);   // lo*hi
                    mma_tf32(acc[ma][na], ah, bl[na]);   // hi*lo
                }
            }
        }
        __syncthreads();
    }
#undef LOAD_STAGE

    // epilogue: c0=(r,c) c1=(r,c+1) c2=(r+8,c) c3=(r+8,c+1)
    const int rbase = row0 + wm * 64 + (lane >> 2);
    const int cbase = col0 + wn * 32 + 2 * (lane & 3);
#pragma unroll
    for (int ma = 0; ma < 4; ma++) {
#pragma unroll
        for (int na = 0; na < 4; na++) {
#pragma unroll
            for (int i = 0; i < 2; i++) {
#pragma unroll
                for (int j = 0; j < 2; j++) {
                    int r = rbase + ma * 16 + i * 8;
                    int c = cbase + na * 8 + j;
                    float v = acc[ma][na][i * 2 + j] + bias[c];
                    if (MODE == 0) {
                        C[(size_t)r * N + c] = v;
                    } else {
                        int arow = r & 4095;     // a'
                        int ob   = r >> 12;      // b
                        C[(size_t)arow * (BATCH * DM) + (size_t)ob * DM + c] = v;
                    }
                }
            }
        }
    }
}

__global__ __launch_bounds__(256, 2)
void qkv_gemm(const float* __restrict__ q, const float* __restrict__ k,
              const float* __restrict__ v,
              const float* __restrict__ Wq, const float* __restrict__ bq,
              const float* __restrict__ Wk, const float* __restrict__ bk,
              const float* __restrict__ Wv, const float* __restrict__ bv)
{
    const float* A; const float* B; const float* bias; float* C;
    if (blockIdx.z == 0)      { A = q; B = Wq; bias = bq; C = g_Q; }
    else if (blockIdx.z == 1) { A = k; B = Wk; bias = bk; C = g_K; }
    else                      { A = v; B = Wv; bias = bv; C = g_V; }
    tgemm_body<0>(A, B, bias, C, DM, DM);
}

__global__ __launch_bounds__(256, 2)
void out_gemm(const float* __restrict__ Wo, const float* __restrict__ bo,
              float* __restrict__ out)
{
    tgemm_body<1>(g_AO, Wo, bo, out, DM, DM);
}

// ---------------- attention: per (a,b) pair, 16x16 scores across HEADS ------
// One warp per pair, 2 warps per block. Exact sparsemax (sort-based simplex
// projection) over 16-wide rows with combined scale 1/(sqrt(64)*alpha)=1/12.
// Output written directly in the bug-faithful permuted layout:
//   g_AO[(b*4096 + h*256 + a/16)*1024 + (a%16)*64 + d]
__global__ void attn_kernel()
{
    __shared__ float qs[2][16][65];
    __shared__ float ks[2][16][65];
    __shared__ float vs[2][16][65];
    __shared__ float ss[2][16][17];

    const int w = threadIdx.x >> 5;      // warp in block (0..1)
    const int l = threadIdx.x & 31;      // lane
    const int p = blockIdx.x * 2 + w;    // pair id 0..32767
    const int a = p >> 3;
    const int b = p & 7;

    const float* Qg = g_Q + (size_t)p * DM;
    const float* Kg = g_K + (size_t)p * DM;
    const float* Vg = g_V + (size_t)p * DM;

#pragma unroll
    for (int i = 0; i < 8; i++) {
        int idx4 = (l + 32 * i) * 4;
        int r = idx4 >> 6, c = idx4 & 63;
        float4 vq = *(const float4*)(Qg + idx4);
        qs[w][r][c] = vq.x; qs[w][r][c+1] = vq.y; qs[w][r][c+2] = vq.z; qs[w][r][c+3] = vq.w;
        float4 vk = *(const float4*)(Kg + idx4);
        ks[w][r][c] = vk.x; ks[w][r][c+1] = vk.y; ks[w][r][c+2] = vk.z; ks[w][r][c+3] = vk.w;
        float4 vv = *(const float4*)(Vg + idx4);
        vs[w][r][c] = vv.x; vs[w][r][c+1] = vv.y; vs[w][r][c+2] = vv.z; vs[w][r][c+3] = vv.w;
    }
    __syncwarp();

    // scores: lane l owns (h = l>>1, g in [(l&1)*8, +8))
    {
        const int h  = l >> 1;
        const int g0 = (l & 1) * 8;
        float acc[8] = {0, 0, 0, 0, 0, 0, 0, 0};
#pragma unroll
        for (int d = 0; d < 64; d++) {
            float qv = qs[w][h][d];
#pragma unroll
            for (int j = 0; j < 8; j++) acc[j] += qv * ks[w][g0 + j][d];
        }
        const float sc = 1.0f / 12.0f;   // 1/(sqrt(64)*alpha)
#pragma unroll
        for (int j = 0; j < 8; j++) ss[w][h][g0 + j] = acc[j] * sc;
    }
    __syncwarp();

    // sparsemax per row: lanes 0..15, one row each
    if (l < 16) {
        float z[16];
#pragma unroll
        for (int g = 0; g < 16; g++) z[g] = ss[w][l][g];
#pragma unroll
        for (int i = 0; i < 15; i++)
#pragma unroll
            for (int j = i + 1; j < 16; j++)
                if (z[j] > z[i]) { float t = z[i]; z[i] = z[j]; z[j] = t; }
        float cum = 0.0f, tausum = 0.0f;
        int kk = 0;
#pragma unroll
        for (int i = 0; i < 16; i++) {
            cum += z[i];
            if (z[i] * (float)(i + 1) > cum - 1.0f) { kk = i + 1; tausum = cum; }
        }
        float tau = (tausum - 1.0f) / (float)kk;
#pragma unroll
        for (int g = 0; g < 16; g++)
            ss[w][l][g] = fmaxf(ss[w][l][g] - tau, 0.0f);
    }
    __syncwarp();

    // attn_out: lane l owns (h = l>>1, d in [(l&1)*32, +32))
    {
        const int h  = l >> 1;
        const int d0 = (l & 1) * 32;
        float o[32];
#pragma unroll
        for (int d = 0; d < 32; d++) o[d] = 0.0f;
#pragma unroll
        for (int g = 0; g < 16; g++) {
            float av = ss[w][h][g];
#pragma unroll
            for (int d = 0; d < 32; d++) o[d] += av * vs[w][g][d0 + d];
        }
        const int rowp = b * 4096 + h * 256 + (a >> 4);
        const int colb = (a & 15) * 64 + d0;
        float* dst = g_AO + (size_t)rowp * DM + colb;
#pragma unroll
        for (int d4 = 0; d4 < 32; d4 += 4) {
            float4 v4 = make_float4(o[d4], o[d4 + 1], o[d4 + 2], o[d4 + 3]);
            *(float4*)(dst + d4) = v4;
        }
    }
}

// ---------------- launch -----------------------------------------------------
extern "C" void kernel_launch(void* const* d_in, const int* in_sizes, int n_in,
                              void* d_out, int out_size)
{
    const float* query = (const float*)d_in[0];
    const float* key   = (const float*)d_in[1];
    const float* value = (const float*)d_in[2];
    const float* Wq = (const float*)d_in[3];
    const float* bq = (const float*)d_in[4];
    const float* Wk = (const float*)d_in[5];
    const float* bk = (const float*)d_in[6];
    const float* Wv = (const float*)d_in[7];
    const float* bv = (const float*)d_in[8];
    const float* Wo = (const float*)d_in[9];
    const float* bo = (const float*)d_in[10];
    float* out = (float*)d_out;

    static bool attr_done = false;
    if (!attr_done) {
        cudaFuncSetAttribute(qkv_gemm, cudaFuncAttributeMaxDynamicSharedMemorySize, SMEM_BYTES);
        cudaFuncSetAttribute(out_gemm, cudaFuncAttributeMaxDynamicSharedMemorySize, SMEM_BYTES);
        attr_done = true;
    }

    // Q/K/V projections: 3 x (32768x1024x1024) NT GEMM, 3xTF32 tensor cores
    dim3 g1(DM / 128, MTOT / 128, 3);
    qkv_gemm<<<g1, 256, SMEM_BYTES>>>(query, key, value, Wq, bq, Wk, bk, Wv, bv);

    // attention + sparsemax + permuted scratch write
    attn_kernel<<<MTOT / 2, 64>>>();

    // output projection with final (A,B,D) transpose in epilogue
    dim3 g2(DM / 128, MTOT / 128, 1);
    out_gemm<<<g2, 256, SMEM_BYTES>>>(Wo, bo, out);
}